// round 7
// baseline (speedup 1.0000x reference)
#include <cuda_runtime.h>
#include <cuda_bf16.h>
#include <cstdint>

#define MAXN 100096

__device__ unsigned char g_ind0[MAXN];
__device__ unsigned char g_ind1[MAXN];
__device__ volatile unsigned int g_bar;
__device__ unsigned int g_tilectr;

__device__ __forceinline__ void mma16816(float* c, const unsigned* a, const unsigned* b) {
    asm volatile(
        "mma.sync.aligned.m16n8k16.row.col.f32.bf16.bf16.f32 "
        "{%0,%1,%2,%3},{%4,%5,%6,%7},{%8,%9},{%0,%1,%2,%3};\n"
        : "+f"(c[0]), "+f"(c[1]), "+f"(c[2]), "+f"(c[3])
        : "r"(a[0]), "r"(a[1]), "r"(a[2]), "r"(a[3]), "r"(b[0]), "r"(b[1]));
}

__device__ __forceinline__ float bfl(unsigned u) {
    return __bfloat162float(__ushort_as_bfloat16((unsigned short)(u & 0xffffu)));
}
__device__ __forceinline__ float bfh(unsigned u) {
    return __bfloat162float(__ushort_as_bfloat16((unsigned short)(u >> 16)));
}

// fp32 pair -> bf16 hi (round-to-nearest) + bf16 lo residual
__device__ __forceinline__ void split2(float2 f, unsigned& hi, unsigned& lo) {
    unsigned u0 = __float_as_uint(f.x) + 0x8000u;
    unsigned u1 = __float_as_uint(f.y) + 0x8000u;
    asm("prmt.b32 %0,%1,%2,0x7632;" : "=r"(hi) : "r"(u0), "r"(u1));
    float l0 = f.x - __uint_as_float(u0 & 0xffff0000u);
    float l1 = f.y - __uint_as_float(u1 & 0xffff0000u);
    asm("cvt.rn.bf16x2.f32 %0, %1, %2;" : "=r"(lo) : "f"(l1), "f"(l0));
}

// Software grid barrier: grid <= #SMs, 1 block/SM -> all co-resident.
__device__ __forceinline__ void grid_bar(unsigned nb) {
    __syncthreads();
    if (threadIdx.x == 0) {
        __threadfence();
        unsigned old = atomicAdd((unsigned*)&g_bar, 1u);
        unsigned target = (old / nb + 1u) * nb;
        while (g_bar < target) { }
        __threadfence();
    }
    __syncthreads();
}

// smem layout (u32 units) -- no A staging / fragments: A lives in registers
#define BHI_OFF   0        // 9216 : B-ext hi frags (18 n-tiles x 8 kc x 32 x uint2)
#define BLO_OFF   9216     // 9216
#define RED_OFF   18432    // 1536 floats : per-node sv[4](+ch), sf[4], al[4]
#define GBUF_OFF  19968    // 1152 floats : per-node g01[4], b2[4] (pitch 9)
#define BRS_OFF   21120    // 128
#define QS_OFF    21248    // 512
#define CHS_OFF   21760    // 8
#define STILE_OFF 21768    // 1  : stolen tile index broadcast
#define SMEM_U32  21772    // 87088 bytes

// Persistent kernel: flag phases (grid barriers) then work-stolen 128-node
// tiles of fused GEMM + beta-softmax + epilogue.
// Warp mapping: m = warp&7 (one 16-row m-tile), half = warp>>3 (n-tile group).
// Each warp: 9 n-tiles (half*8+0..7 outputs, 16+half extras) -> balanced.
__global__ void __launch_bounds__(512, 1) fused_kernel(
    const float* __restrict__ feat, const float* __restrict__ Wr,
    const float* __restrict__ br, const float* __restrict__ rl,
    const float* __restrict__ rr,
    const int* __restrict__ d0, int E0, const int* __restrict__ d1, int E1,
    float* __restrict__ out, int N)
{
    extern __shared__ unsigned smem_u[];
    unsigned* BHI = smem_u + BHI_OFF;
    unsigned* BLO = smem_u + BLO_OFF;
    float* red  = (float*)(smem_u + RED_OFF);
    float* gbuf = (float*)(smem_u + GBUF_OFF);
    float* br_s = (float*)(smem_u + BRS_OFF);
    float* q_s  = (float*)(smem_u + QS_OFF);
    float* ch_s = (float*)(smem_u + CHS_OFF);
    volatile int* s_tile = (volatile int*)(smem_u + STILE_OFF);

    const int tid  = threadIdx.x;
    const int lane = tid & 31;
    const int warp = tid >> 5;
    const int m    = warp & 7;
    const int half = warp >> 3;
    const unsigned nb = gridDim.x;

    // ---- phase 0: zero flags; reset tile counter
    for (int i = blockIdx.x * 512 + tid; i < MAXN / 4; i += nb * 512) {
        ((unsigned*)g_ind0)[i] = 0u;
        ((unsigned*)g_ind1)[i] = 0u;
    }
    if (blockIdx.x == 0 && tid == 0) g_tilectr = 0u;
    grid_bar(nb);

    // ---- phase 1: mark flags
    for (int i = blockIdx.x * 512 + tid; i < E0 + E1; i += nb * 512) {
        if (i < E0) g_ind0[d0[i]] = 1;
        else        g_ind1[d1[i - E0]] = 1;
    }

    // ---- prologue (overlaps other blocks' marking)
    if (tid < 128) br_s[tid] = br[tid];
    __syncthreads();
    if (tid < 512) {
        int h = tid >> 7, k = tid & 127;
        float s = 0.f;
        #pragma unroll 4
        for (int t = 0; t < 32; t++)
            s += __ldg(&Wr[(h * 32 + t) * 128 + k]) * __ldg(&rr[h * 32 + t]);
        q_s[tid] = s;
    }
    if (tid < 4) {
        float s = 0.f;
        for (int t = 0; t < 32; t++)
            s += __ldg(&br[tid * 32 + t]) * __ldg(&rr[tid * 32 + t]);
        ch_s[tid] = s;
    }
    __syncthreads();

    // B-ext fragments: t'<128 Wr; 128-131 q_h; 132-135 rr head-masked;
    // 136-139 rl head-masked; 140-143 zero. Stored in mma fragment layout.
    for (int i = tid; i < 9216; i += 512) {
        int j  = i & 1;
        int ln = (i >> 1) & 31;
        int kc = (i >> 6) & 7;
        int nt = i >> 9;
        int tp = nt * 8 + (ln >> 2);
        int k0 = kc * 16 + (ln & 3) * 2 + j * 8;
        float v[2];
        #pragma unroll
        for (int e = 0; e < 2; e++) {
            int k = k0 + e;
            float x;
            if (tp < 128)      x = __ldg(&Wr[tp * 128 + k]);
            else if (tp < 132) x = q_s[(tp - 128) * 128 + k];
            else if (tp < 136) x = ((k >> 5) == (tp - 132)) ? __ldg(&rr[k]) : 0.f;
            else if (tp < 140) x = ((k >> 5) == (tp - 136)) ? __ldg(&rl[k]) : 0.f;
            else               x = 0.f;
            v[e] = x;
        }
        unsigned hi, lo;
        split2(make_float2(v[0], v[1]), hi, lo);
        BHI[i] = hi;
        BLO[i] = lo;
    }

    grid_bar(nb);   // marking done everywhere; B frags visible

    // ---- main loop: work-stolen tiles
    const int T = (N + 127) >> 7;
    const uint2* bhp0 = ((const uint2*)BHI) + (16 + half) * 256 + lane;
    const uint2* blp0 = ((const uint2*)BLO) + (16 + half) * 256 + lane;
    const uint2* bhpO = ((const uint2*)BHI) + (half * 8) * 256 + lane;
    const uint2* blpO = ((const uint2*)BLO) + (half * 8) * 256 + lane;

    for (;;) {
        __syncthreads();   // red/gbuf free; s_tile consumed
        if (tid == 0) *s_tile = (int)atomicAdd(&g_tilectr, 1u);
        __syncthreads();
        const int tile = *s_tile;
        if (tile >= T) break;

        // ---- load this thread's 2 feat rows, split to A hi/lo registers
        // rows: m*16 + (lane>>2) and +8 ; cols per kc: kc*16+(lane&3)*2 {+0,+1,+8,+9}
        uint4 Ah[8], Al[8];
        {
            long n0 = (long)tile * 128 + m * 16 + (lane >> 2);
            long n1 = n0 + 8;
            if (n0 > N - 1) n0 = N - 1;
            if (n1 > N - 1) n1 = N - 1;
            const float2* f0p = (const float2*)(feat + n0 * 128) + (lane & 3);
            const float2* f1p = (const float2*)(feat + n1 * 128) + (lane & 3);
            #pragma unroll
            for (int kc = 0; kc < 8; kc++) {
                float2 a = __ldg(&f0p[kc * 8]);
                float2 b = __ldg(&f1p[kc * 8]);
                float2 c = __ldg(&f0p[kc * 8 + 4]);
                float2 d = __ldg(&f1p[kc * 8 + 4]);
                split2(a, Ah[kc].x, Al[kc].x);
                split2(b, Ah[kc].y, Al[kc].y);
                split2(c, Ah[kc].z, Al[kc].z);
                split2(d, Ah[kc].w, Al[kc].w);
            }
        }

        // ---- MMA: 1 m-tile x 9 n-tiles, 3-term bf16 split; A from regs
        float acc[9][4];
        #pragma unroll
        for (int i = 0; i < 9; i++)
            #pragma unroll
            for (int c = 0; c < 4; c++) acc[i][c] = 0.f;

        #pragma unroll
        for (int kc = 0; kc < 8; kc++) {
            #pragma unroll
            for (int i = 0; i < 8; i++) {
                uint2 bh = bhpO[(i * 8 + kc) * 32];
                uint2 bl = blpO[(i * 8 + kc) * 32];
                mma16816(acc[i], (const unsigned*)&Ah[kc], (const unsigned*)&bh);
                mma16816(acc[i], (const unsigned*)&Ah[kc], (const unsigned*)&bl);
                mma16816(acc[i], (const unsigned*)&Al[kc], (const unsigned*)&bh);
            }
            {
                uint2 bh = bhp0[kc * 32];
                uint2 bl = blp0[kc * 32];
                mma16816(acc[8], (const unsigned*)&Ah[kc], (const unsigned*)&bh);
                mma16816(acc[8], (const unsigned*)&Ah[kc], (const unsigned*)&bl);
                mma16816(acc[8], (const unsigned*)&Al[kc], (const unsigned*)&bh);
            }
        }

        // ---- extras: half0 -> gnt16 (sv+ch cols 0-3, sf cols 4-7),
        //              half1 -> gnt17 (al cols 0-3)
        {
            int cidx = (lane & 3) * 2;
            #pragma unroll
            for (int j0 = 0; j0 < 2; j0++) {
                int nl = m * 16 + (lane >> 2) + 8 * j0;
                float s0 = acc[8][2 * j0];
                float s1 = acc[8][2 * j0 + 1];
                if (half == 0) {
                    if (cidx < 4) { s0 += ch_s[cidx]; s1 += ch_s[cidx + 1]; }
                    red[nl * 12 + cidx]     = s0;
                    red[nl * 12 + cidx + 1] = s1;
                } else if (cidx < 4) {
                    red[nl * 12 + 8 + cidx]     = s0;
                    red[nl * 12 + 8 + cidx + 1] = s1;
                }
            }
        }
        __syncthreads();

        // ---- beta softmax over heads; fold flags into g01/b2
        if (tid < 128) {
            long ng = (long)tile * 128 + tid;
            int cn = ng < N ? (int)ng : N - 1;
            float i0 = (float)g_ind0[cn];
            float i1 = (float)g_ind1[cn];
            const float* r = &red[tid * 12];
            float sv[4], sf[4], al[4];
            #pragma unroll
            for (int h = 0; h < 4; h++) {
                sv[h] = r[h]; sf[h] = r[4 + h]; al[h] = r[8 + h];
            }
            float bta[3][4];
            #pragma unroll
            for (int jr = 0; jr < 3; jr++) {
                float x[4];
                #pragma unroll
                for (int h = 0; h < 4; h++) {
                    float ar = (jr == 0) ? i0 * sv[h] : (jr == 1) ? i1 * sv[h] : sf[h];
                    float xx = al[h] + ar;
                    x[h] = (xx > 0.f) ? xx : 0.2f * xx;
                }
                float mx = fmaxf(fmaxf(x[0], x[1]), fmaxf(x[2], x[3]));
                float e0 = __expf(x[0] - mx), e1 = __expf(x[1] - mx);
                float e2 = __expf(x[2] - mx), e3 = __expf(x[3] - mx);
                float inv = 1.f / (e0 + e1 + e2 + e3);
                bta[jr][0] = e0 * inv; bta[jr][1] = e1 * inv;
                bta[jr][2] = e2 * inv; bta[jr][3] = e3 * inv;
            }
            #pragma unroll
            for (int h = 0; h < 4; h++) {
                gbuf[tid * 9 + h]     = bta[0][h] * i0 + bta[1][h] * i1;
                gbuf[tid * 9 + 4 + h] = bta[2][h];
            }
        }
        __syncthreads();

        // ---- output: relu(g01*(v+br) + b2*feat); feat from this thread's regs
        #pragma unroll
        for (int ip = 0; ip < 4; ip++) {
            uint4 fh4 = half ? Ah[4 + ip] : Ah[ip];
            uint4 fl4 = half ? Al[4 + ip] : Al[ip];
            const unsigned* fh = (const unsigned*)&fh4;
            const unsigned* fl = (const unsigned*)&fl4;
            #pragma unroll
            for (int iodd = 0; iodd < 2; iodd++) {
                int i = 2 * ip + iodd;
                int gnt = half * 8 + i;
                int head = gnt >> 2;
                int tcol = gnt * 8 + (lane & 3) * 2;
                float2 brv = *(const float2*)&br_s[tcol];
                #pragma unroll
                for (int j0 = 0; j0 < 2; j0++) {
                    int nl = m * 16 + (lane >> 2) + 8 * j0;
                    long ng = (long)tile * 128 + nl;
                    if (ng < N) {
                        int j = j0 + 2 * iodd;
                        float f0 = bfl(fh[j]) + bfl(fl[j]);
                        float f1 = bfh(fh[j]) + bfh(fl[j]);
                        float g01 = gbuf[nl * 9 + head];
                        float b2v = gbuf[nl * 9 + 4 + head];
                        float v0 = acc[i][2 * j0]     + brv.x;
                        float v1 = acc[i][2 * j0 + 1] + brv.y;
                        float o0 = fmaxf(fmaf(g01, v0, b2v * f0), 0.f);
                        float o1 = fmaxf(fmaf(g01, v1, b2v * f1), 0.f);
                        *(float2*)&out[ng * 128 + tcol] = make_float2(o0, o1);
                    }
                }
            }
        }
    }
}

extern "C" void kernel_launch(void* const* d_in, const int* in_sizes, int n_in,
                              void* d_out, int out_size) {
    // Inputs: feat, Wl, bl, Wr, br, attn_l, attn_r, rel_attn_l, rel_attn_r,
    //         alpha, src0, dst0, src1, dst1
    const float* feat = (const float*)d_in[0];
    const float* Wr   = (const float*)d_in[3];
    const float* br   = (const float*)d_in[4];
    const float* rl   = (const float*)d_in[7];
    const float* rr   = (const float*)d_in[8];
    const int* dst0   = (const int*)d_in[11];
    const int* dst1   = (const int*)d_in[13];
    float* out        = (float*)d_out;

    const int N  = in_sizes[0] / 128;
    const int E0 = in_sizes[11];
    const int E1 = in_sizes[13];

    const int SMEM_BYTES = SMEM_U32 * 4;
    cudaFuncSetAttribute(fused_kernel,
                         cudaFuncAttributeMaxDynamicSharedMemorySize, SMEM_BYTES);
    int nsm = 148;
    cudaDeviceGetAttribute(&nsm, cudaDevAttrMultiProcessorCount, 0);
    int T = (N + 127) >> 7;
    int grid = nsm < T ? nsm : T;
    fused_kernel<<<grid, 512, SMEM_BYTES>>>(feat, Wr, br, rl, rr,
                                            dst0, E0, dst1, E1, out, N);
}

// round 10
// speedup vs baseline: 1.0924x; 1.0924x over previous
#include <cuda_runtime.h>
#include <cuda_fp16.h>
#include <cstdint>

#define MAXN 100096

__device__ unsigned char g_ind0[MAXN];
__device__ unsigned char g_ind1[MAXN];
__device__ volatile unsigned int g_bar;
__device__ unsigned int g_tilectr;

// f16 x f16 -> f32 mma
__device__ __forceinline__ void mma_f16(float* c, const unsigned* a, const unsigned* b) {
    asm volatile(
        "mma.sync.aligned.m16n8k16.row.col.f32.f16.f16.f32 "
        "{%0,%1,%2,%3},{%4,%5,%6,%7},{%8,%9},{%0,%1,%2,%3};\n"
        : "+f"(c[0]), "+f"(c[1]), "+f"(c[2]), "+f"(c[3])
        : "r"(a[0]), "r"(a[1]), "r"(a[2]), "r"(a[3]), "r"(b[0]), "r"(b[1]));
}

__device__ __forceinline__ float hfl(unsigned u) {
    return __half2float(__ushort_as_half((unsigned short)(u & 0xffffu)));
}
__device__ __forceinline__ float hfh(unsigned u) {
    return __half2float(__ushort_as_half((unsigned short)(u >> 16)));
}

// fp32 pair -> fp16 hi (RN) + fp16 lo residual (A-side 2-term split)
__device__ __forceinline__ void split2h(float2 f, unsigned& hi, unsigned& lo) {
    asm("cvt.rn.f16x2.f32 %0, %1, %2;" : "=r"(hi) : "f"(f.y), "f"(f.x));
    float r0 = f.x - hfl(hi);
    float r1 = f.y - hfh(hi);
    asm("cvt.rn.f16x2.f32 %0, %1, %2;" : "=r"(lo) : "f"(r1), "f"(r0));
}

// Software grid barrier: grid <= #SMs, 1 block/SM -> all co-resident.
__device__ __forceinline__ void grid_bar(unsigned nb) {
    __syncthreads();
    if (threadIdx.x == 0) {
        __threadfence();
        unsigned old = atomicAdd((unsigned*)&g_bar, 1u);
        unsigned target = (old / nb + 1u) * nb;
        while (g_bar < target) { }
        __threadfence();
    }
    __syncthreads();
}

// smem layout (u32 units) -- A in registers; B single fp16 copy
#define BF_OFF    0        // 9216 : B-ext frags fp16 (18 n-tiles x 8 kc x 32 x uint2)
#define RED_OFF   9216     // 1536 floats : per-node sv[4](+ch), sf[4], al[4]
#define GBUF_OFF  10752    // 1152 floats : per-node g01[4], b2[4] (pitch 9)
#define BRS_OFF   11904    // 128
#define QS_OFF    12032    // 512
#define CHS_OFF   12544    // 8
#define STILE_OFF 12552    // 1
#define SMEM_U32  12556    // 50224 bytes

// Persistent kernel: flag phases (grid barriers) then work-stolen 128-node
// tiles of fused GEMM + beta-softmax + epilogue.
// Warp mapping: m = warp&7 (16-row m-tile), half = warp>>3 (n-tile group).
// Each warp: 9 n-tiles (half*8+0..7 outputs, 16+half extras).
__global__ void __launch_bounds__(512, 1) fused_kernel(
    const float* __restrict__ feat, const float* __restrict__ Wr,
    const float* __restrict__ br, const float* __restrict__ rl,
    const float* __restrict__ rr,
    const int* __restrict__ d0, int E0, const int* __restrict__ d1, int E1,
    float* __restrict__ out, int N)
{
    extern __shared__ unsigned smem_u[];
    unsigned* BF = smem_u + BF_OFF;
    float* red  = (float*)(smem_u + RED_OFF);
    float* gbuf = (float*)(smem_u + GBUF_OFF);
    float* br_s = (float*)(smem_u + BRS_OFF);
    float* q_s  = (float*)(smem_u + QS_OFF);
    float* ch_s = (float*)(smem_u + CHS_OFF);
    volatile int* s_tile = (volatile int*)(smem_u + STILE_OFF);

    const int tid  = threadIdx.x;
    const int lane = tid & 31;
    const int warp = tid >> 5;
    const int m    = warp & 7;
    const int half = warp >> 3;
    const unsigned nb = gridDim.x;

    // ---- phase 0: zero flags; reset tile counter
    for (int i = blockIdx.x * 512 + tid; i < MAXN / 4; i += nb * 512) {
        ((unsigned*)g_ind0)[i] = 0u;
        ((unsigned*)g_ind1)[i] = 0u;
    }
    if (blockIdx.x == 0 && tid == 0) g_tilectr = 0u;
    grid_bar(nb);

    // ---- phase 1: mark flags
    for (int i = blockIdx.x * 512 + tid; i < E0 + E1; i += nb * 512) {
        if (i < E0) g_ind0[d0[i]] = 1;
        else        g_ind1[d1[i - E0]] = 1;
    }

    // ---- prologue (overlaps other blocks' marking)
    if (tid < 128) br_s[tid] = br[tid];
    __syncthreads();
    if (tid < 512) {
        int h = tid >> 7, k = tid & 127;
        float s = 0.f;
        #pragma unroll 4
        for (int t = 0; t < 32; t++)
            s += __ldg(&Wr[(h * 32 + t) * 128 + k]) * __ldg(&rr[h * 32 + t]);
        q_s[tid] = s;
    }
    if (tid < 4) {
        float s = 0.f;
        for (int t = 0; t < 32; t++)
            s += __ldg(&br[tid * 32 + t]) * __ldg(&rr[tid * 32 + t]);
        ch_s[tid] = s;
    }
    __syncthreads();

    // B-ext fragments (single fp16): t'<128 Wr; 128-131 q_h; 132-135 rr
    // head-masked; 136-139 rl head-masked; 140-143 zero. mma fragment layout.
    for (int i = tid; i < 9216; i += 512) {
        int j  = i & 1;
        int ln = (i >> 1) & 31;
        int kc = (i >> 6) & 7;
        int nt = i >> 9;
        int tp = nt * 8 + (ln >> 2);
        int k0 = kc * 16 + (ln & 3) * 2 + j * 8;
        float v[2];
        #pragma unroll
        for (int e = 0; e < 2; e++) {
            int k = k0 + e;
            float x;
            if (tp < 128)      x = __ldg(&Wr[tp * 128 + k]);
            else if (tp < 132) x = q_s[(tp - 128) * 128 + k];
            else if (tp < 136) x = ((k >> 5) == (tp - 132)) ? __ldg(&rr[k]) : 0.f;
            else if (tp < 140) x = ((k >> 5) == (tp - 136)) ? __ldg(&rl[k]) : 0.f;
            else               x = 0.f;
            v[e] = x;
        }
        unsigned b;
        asm("cvt.rn.f16x2.f32 %0, %1, %2;" : "=r"(b) : "f"(v[1]), "f"(v[0]));
        BF[i] = b;
    }

    grid_bar(nb);   // marking done everywhere; B frags visible

    // ---- main loop: work-stolen tiles
    const int T = (N + 127) >> 7;
    const uint2* bpx = ((const uint2*)BF) + (16 + half) * 256 + lane;
    const uint2* bpO = ((const uint2*)BF) + (half * 8) * 256 + lane;

    for (;;) {
        __syncthreads();   // red/gbuf free; s_tile consumed
        if (tid == 0) *s_tile = (int)atomicAdd(&g_tilectr, 1u);
        __syncthreads();
        const int tile = *s_tile;
        if (tile >= T) break;

        // ---- load this thread's 2 feat rows, split to fp16 hi/lo registers
        // rows: m*16 + (lane>>2) and +8 ; cols per kc: kc*16+(lane&3)*2 {+0,+1,+8,+9}
        uint4 Ah[8], Al[8];
        {
            long n0 = (long)tile * 128 + m * 16 + (lane >> 2);
            long n1 = n0 + 8;
            if (n0 > N - 1) n0 = N - 1;
            if (n1 > N - 1) n1 = N - 1;
            const float2* f0p = (const float2*)(feat + n0 * 128) + (lane & 3);
            const float2* f1p = (const float2*)(feat + n1 * 128) + (lane & 3);
            #pragma unroll
            for (int kc = 0; kc < 8; kc++) {
                float2 a = __ldg(&f0p[kc * 8]);
                float2 b = __ldg(&f1p[kc * 8]);
                float2 c = __ldg(&f0p[kc * 8 + 4]);
                float2 d = __ldg(&f1p[kc * 8 + 4]);
                split2h(a, Ah[kc].x, Al[kc].x);
                split2h(b, Ah[kc].y, Al[kc].y);
                split2h(c, Ah[kc].z, Al[kc].z);
                split2h(d, Ah[kc].w, Al[kc].w);
            }
        }

        // ---- MMA: 1 m-tile x 9 n-tiles, 2-term fp16 split; A from regs
        float acc[9][4];
        #pragma unroll
        for (int i = 0; i < 9; i++)
            #pragma unroll
            for (int c = 0; c < 4; c++) acc[i][c] = 0.f;

        #pragma unroll
        for (int kc = 0; kc < 8; kc++) {
            #pragma unroll
            for (int i = 0; i < 8; i++) {
                uint2 b = bpO[(i * 8 + kc) * 32];
                mma_f16(acc[i], (const unsigned*)&Ah[kc], (const unsigned*)&b);
                mma_f16(acc[i], (const unsigned*)&Al[kc], (const unsigned*)&b);
            }
            {
                uint2 b = bpx[kc * 32];
                mma_f16(acc[8], (const unsigned*)&Ah[kc], (const unsigned*)&b);
                mma_f16(acc[8], (const unsigned*)&Al[kc], (const unsigned*)&b);
            }
        }

        // ---- extras: half0 -> gnt16 (sv+ch cols 0-3, sf cols 4-7),
        //              half1 -> gnt17 (al cols 0-3)
        {
            int cidx = (lane & 3) * 2;
            #pragma unroll
            for (int j0 = 0; j0 < 2; j0++) {
                int nl = m * 16 + (lane >> 2) + 8 * j0;
                float s0 = acc[8][2 * j0];
                float s1 = acc[8][2 * j0 + 1];
                if (half == 0) {
                    if (cidx < 4) { s0 += ch_s[cidx]; s1 += ch_s[cidx + 1]; }
                    red[nl * 12 + cidx]     = s0;
                    red[nl * 12 + cidx + 1] = s1;
                } else if (cidx < 4) {
                    red[nl * 12 + 8 + cidx]     = s0;
                    red[nl * 12 + 8 + cidx + 1] = s1;
                }
            }
        }
        __syncthreads();

        // ---- beta softmax over heads; fold flags into g01/b2
        if (tid < 128) {
            long ng = (long)tile * 128 + tid;
            int cn = ng < N ? (int)ng : N - 1;
            float i0 = (float)g_ind0[cn];
            float i1 = (float)g_ind1[cn];
            const float* r = &red[tid * 12];
            float sv[4], sf[4], al[4];
            #pragma unroll
            for (int h = 0; h < 4; h++) {
                sv[h] = r[h]; sf[h] = r[4 + h]; al[h] = r[8 + h];
            }
            float bta[3][4];
            #pragma unroll
            for (int jr = 0; jr < 3; jr++) {
                float x[4];
                #pragma unroll
                for (int h = 0; h < 4; h++) {
                    float ar = (jr == 0) ? i0 * sv[h] : (jr == 1) ? i1 * sv[h] : sf[h];
                    float xx = al[h] + ar;
                    x[h] = (xx > 0.f) ? xx : 0.2f * xx;
                }
                float mx = fmaxf(fmaxf(x[0], x[1]), fmaxf(x[2], x[3]));
                float e0 = __expf(x[0] - mx), e1 = __expf(x[1] - mx);
                float e2 = __expf(x[2] - mx), e3 = __expf(x[3] - mx);
                float inv = 1.f / (e0 + e1 + e2 + e3);
                bta[jr][0] = e0 * inv; bta[jr][1] = e1 * inv;
                bta[jr][2] = e2 * inv; bta[jr][3] = e3 * inv;
            }
            #pragma unroll
            for (int h = 0; h < 4; h++) {
                gbuf[tid * 9 + h]     = bta[0][h] * i0 + bta[1][h] * i1;
                gbuf[tid * 9 + 4 + h] = bta[2][h];
            }
        }
        __syncthreads();

        // ---- output: relu(g01*(v+br) + b2*feat); feat from this thread's regs
        // (hi+lo reconstruction is exact to 2^-22)
        #pragma unroll
        for (int ip = 0; ip < 4; ip++) {
            uint4 fh4 = half ? Ah[4 + ip] : Ah[ip];
            uint4 fl4 = half ? Al[4 + ip] : Al[ip];
            const unsigned* fh = (const unsigned*)&fh4;
            const unsigned* fl = (const unsigned*)&fl4;
            #pragma unroll
            for (int iodd = 0; iodd < 2; iodd++) {
                int i = 2 * ip + iodd;
                int gnt = half * 8 + i;
                int head = gnt >> 2;
                int tcol = gnt * 8 + (lane & 3) * 2;
                float2 brv = *(const float2*)&br_s[tcol];
                #pragma unroll
                for (int j0 = 0; j0 < 2; j0++) {
                    int nl = m * 16 + (lane >> 2) + 8 * j0;
                    long ng = (long)tile * 128 + nl;
                    if (ng < N) {
                        int j = j0 + 2 * iodd;
                        float f0 = hfl(fh[j]) + hfl(fl[j]);
                        float f1 = hfh(fh[j]) + hfh(fl[j]);
                        float g01 = gbuf[nl * 9 + head];
                        float b2v = gbuf[nl * 9 + 4 + head];
                        float v0 = acc[i][2 * j0]     + brv.x;
                        float v1 = acc[i][2 * j0 + 1] + brv.y;
                        float o0 = fmaxf(fmaf(g01, v0, b2v * f0), 0.f);
                        float o1 = fmaxf(fmaf(g01, v1, b2v * f1), 0.f);
                        *(float2*)&out[ng * 128 + tcol] = make_float2(o0, o1);
                    }
                }
            }
        }
    }
}

extern "C" void kernel_launch(void* const* d_in, const int* in_sizes, int n_in,
                              void* d_out, int out_size) {
    // Inputs: feat, Wl, bl, Wr, br, attn_l, attn_r, rel_attn_l, rel_attn_r,
    //         alpha, src0, dst0, src1, dst1
    const float* feat = (const float*)d_in[0];
    const float* Wr   = (const float*)d_in[3];
    const float* br   = (const float*)d_in[4];
    const float* rl   = (const float*)d_in[7];
    const float* rr   = (const float*)d_in[8];
    const int* dst0   = (const int*)d_in[11];
    const int* dst1   = (const int*)d_in[13];
    float* out        = (float*)d_out;

    const int N  = in_sizes[0] / 128;
    const int E0 = in_sizes[11];
    const int E1 = in_sizes[13];

    const int SMEM_BYTES = SMEM_U32 * 4;
    cudaFuncSetAttribute(fused_kernel,
                         cudaFuncAttributeMaxDynamicSharedMemorySize, SMEM_BYTES);
    int nsm = 148;
    cudaDeviceGetAttribute(&nsm, cudaDevAttrMultiProcessorCount, 0);
    int T = (N + 127) >> 7;
    int grid = nsm < T ? nsm : T;
    fused_kernel<<<grid, 512, SMEM_BYTES>>>(feat, Wr, br, rl, rr,
                                            dst0, E0, dst1, E1, out, N);
}

// round 11
// speedup vs baseline: 1.2717x; 1.1642x over previous
#include <cuda_runtime.h>
#include <cuda_fp16.h>
#include <cstdint>

#define MAXN 100096

__device__ unsigned char g_ind0[MAXN];
__device__ unsigned char g_ind1[MAXN];
__device__ volatile unsigned int g_bar;
__device__ unsigned int g_tilectr;

// f16 x f16 -> f32 mma
__device__ __forceinline__ void mma_f16(float* c, const unsigned* a, const unsigned* b) {
    asm volatile(
        "mma.sync.aligned.m16n8k16.row.col.f32.f16.f16.f32 "
        "{%0,%1,%2,%3},{%4,%5,%6,%7},{%8,%9},{%0,%1,%2,%3};\n"
        : "+f"(c[0]), "+f"(c[1]), "+f"(c[2]), "+f"(c[3])
        : "r"(a[0]), "r"(a[1]), "r"(a[2]), "r"(a[3]), "r"(b[0]), "r"(b[1]));
}

__device__ __forceinline__ float hfl(unsigned u) {
    return __half2float(__ushort_as_half((unsigned short)(u & 0xffffu)));
}
__device__ __forceinline__ float hfh(unsigned u) {
    return __half2float(__ushort_as_half((unsigned short)(u >> 16)));
}

// fp32 pair -> fp16 hi (RN) + fp16 lo residual
__device__ __forceinline__ void split2h(float2 f, unsigned& hi, unsigned& lo) {
    asm("cvt.rn.f16x2.f32 %0, %1, %2;" : "=r"(hi) : "f"(f.y), "f"(f.x));
    float r0 = f.x - hfl(hi);
    float r1 = f.y - hfh(hi);
    asm("cvt.rn.f16x2.f32 %0, %1, %2;" : "=r"(lo) : "f"(r1), "f"(r0));
}

// Software grid barrier: grid <= #SMs, 1 block/SM -> all co-resident.
__device__ __forceinline__ void grid_bar(unsigned nb) {
    __syncthreads();
    if (threadIdx.x == 0) {
        __threadfence();
        unsigned old = atomicAdd((unsigned*)&g_bar, 1u);
        unsigned target = (old / nb + 1u) * nb;
        while (g_bar < target) { }
        __threadfence();
    }
    __syncthreads();
}

// smem layout (u32 units)
#define BF_OFF    0        // 9216 : B-ext frags fp16 (18 n-tiles x 8 kc x 32 x uint2)
#define RED_OFF   9216     // 3328 : per-warp extras, 16 warps x 16 nodes x pitch 13
#define GBUF_OFF  12544    // 2304 : per-warp g01/b2, 16 warps x 16 nodes x pitch 9
#define BRS_OFF   14848    // 128
#define QS_OFF    14976    // 512
#define CHS_OFF   15488    // 8
#define SMEM_U32  15496    // 61984 bytes

// Persistent kernel. Flag phases use grid barriers; main loop is fully
// warp-autonomous: each warp steals a 16-node group (atomicAdd) and runs
// MMA -> softmax -> epilogue privately (only __syncwarp; NO __syncthreads).
__global__ void __launch_bounds__(512, 1) fused_kernel(
    const float* __restrict__ feat, const float* __restrict__ Wr,
    const float* __restrict__ br, const float* __restrict__ rl,
    const float* __restrict__ rr,
    const int* __restrict__ d0, int E0, const int* __restrict__ d1, int E1,
    float* __restrict__ out, int N)
{
    extern __shared__ unsigned smem_u[];
    unsigned* BF = smem_u + BF_OFF;
    float* red  = (float*)(smem_u + RED_OFF);
    float* gbuf = (float*)(smem_u + GBUF_OFF);
    float* br_s = (float*)(smem_u + BRS_OFF);
    float* q_s  = (float*)(smem_u + QS_OFF);
    float* ch_s = (float*)(smem_u + CHS_OFF);

    const int tid  = threadIdx.x;
    const int lane = tid & 31;
    const int warp = tid >> 5;
    const unsigned nb = gridDim.x;

    // ---- phase 0: zero flags; reset tile counter
    for (int i = blockIdx.x * 512 + tid; i < MAXN / 4; i += nb * 512) {
        ((unsigned*)g_ind0)[i] = 0u;
        ((unsigned*)g_ind1)[i] = 0u;
    }
    if (blockIdx.x == 0 && tid == 0) g_tilectr = 0u;
    grid_bar(nb);

    // ---- phase 1: mark flags
    for (int i = blockIdx.x * 512 + tid; i < E0 + E1; i += nb * 512) {
        if (i < E0) g_ind0[d0[i]] = 1;
        else        g_ind1[d1[i - E0]] = 1;
    }

    // ---- prologue (overlaps other blocks' marking)
    if (tid < 128) br_s[tid] = br[tid];
    __syncthreads();
    if (tid < 512) {
        int h = tid >> 7, k = tid & 127;
        float s = 0.f;
        #pragma unroll 4
        for (int t = 0; t < 32; t++)
            s += __ldg(&Wr[(h * 32 + t) * 128 + k]) * __ldg(&rr[h * 32 + t]);
        q_s[tid] = s;
    }
    if (tid < 4) {
        float s = 0.f;
        for (int t = 0; t < 32; t++)
            s += __ldg(&br[tid * 32 + t]) * __ldg(&rr[tid * 32 + t]);
        ch_s[tid] = s;
    }
    __syncthreads();

    // B-ext fragments (single fp16): t'<128 Wr; 128-131 q_h; 132-135 rr
    // head-masked; 136-139 rl head-masked; 140-143 zero. mma fragment layout.
    for (int i = tid; i < 9216; i += 512) {
        int j  = i & 1;
        int ln = (i >> 1) & 31;
        int kc = (i >> 6) & 7;
        int nt = i >> 9;
        int tp = nt * 8 + (ln >> 2);
        int k0 = kc * 16 + (ln & 3) * 2 + j * 8;
        float v[2];
        #pragma unroll
        for (int e = 0; e < 2; e++) {
            int k = k0 + e;
            float x;
            if (tp < 128)      x = __ldg(&Wr[tp * 128 + k]);
            else if (tp < 132) x = q_s[(tp - 128) * 128 + k];
            else if (tp < 136) x = ((k >> 5) == (tp - 132)) ? __ldg(&rr[k]) : 0.f;
            else if (tp < 140) x = ((k >> 5) == (tp - 136)) ? __ldg(&rl[k]) : 0.f;
            else               x = 0.f;
            v[e] = x;
        }
        unsigned b;
        asm("cvt.rn.f16x2.f32 %0, %1, %2;" : "=r"(b) : "f"(v[1]), "f"(v[0]));
        BF[i] = b;
    }

    grid_bar(nb);   // marking done everywhere; B frags visible

    // ---- main loop: warp-autonomous 16-node groups
    const int T16 = (N + 15) >> 4;
    const uint2* bp = ((const uint2*)BF) + lane;
    float* red_w  = red  + warp * 208;   // 16 nodes x pitch 13
    float* gbuf_w = gbuf + warp * 144;   // 16 nodes x pitch 9
    const int r = lane >> 2;
    const int q = lane & 3;

    for (;;) {
        unsigned g;
        if (lane == 0) g = atomicAdd(&g_tilectr, 1u);
        g = __shfl_sync(0xffffffffu, g, 0);
        if (g >= (unsigned)T16) break;

        long n0 = (long)g * 16 + r;
        long n1 = n0 + 8;
        long c0n = n0 > N - 1 ? N - 1 : n0;
        long c1n = n1 > N - 1 ? N - 1 : n1;
        const float2* f0p = (const float2*)(feat + c0n * 128) + q;
        const float2* f1p = (const float2*)(feat + c1n * 128) + q;

        float acc[18][4];
        #pragma unroll
        for (int i = 0; i < 18; i++)
            #pragma unroll
            for (int c = 0; c < 4; c++) acc[i][c] = 0.f;

        // A streamed per kc with 1-deep prefetch (rows r, r+8 of the group)
        float2 a = __ldg(f0p), b = __ldg(f1p);
        float2 c = __ldg(f0p + 4), d = __ldg(f1p + 4);
        #pragma unroll
        for (int kc = 0; kc < 8; kc++) {
            uint4 Ah, Al;
            split2h(a, Ah.x, Al.x);
            split2h(b, Ah.y, Al.y);
            split2h(c, Ah.z, Al.z);
            split2h(d, Ah.w, Al.w);
            if (kc < 7) {
                a = __ldg(f0p + (kc + 1) * 8);
                b = __ldg(f1p + (kc + 1) * 8);
                c = __ldg(f0p + (kc + 1) * 8 + 4);
                d = __ldg(f1p + (kc + 1) * 8 + 4);
            }
            #pragma unroll
            for (int i = 0; i < 18; i++) {
                uint2 bb = bp[(i * 8 + kc) * 32];
                mma_f16(acc[i], (const unsigned*)&Ah, (const unsigned*)&bb);
                mma_f16(acc[i], (const unsigned*)&Al, (const unsigned*)&bb);
            }
        }

        // ---- extras -> per-warp smem (acc16: sv cols0-3 (+ch), sf cols4-7;
        //      acc17: al cols0-3). Rows r (c0,c1) and r+8 (c2,c3).
        {
            int cidx = q * 2;
            float s0 = acc[16][0], s1 = acc[16][1];
            float s2 = acc[16][2], s3 = acc[16][3];
            if (cidx < 4) {
                float cA = ch_s[cidx], cB = ch_s[cidx + 1];
                s0 += cA; s1 += cB; s2 += cA; s3 += cB;
            }
            red_w[r * 13 + cidx]           = s0;
            red_w[r * 13 + cidx + 1]       = s1;
            red_w[(r + 8) * 13 + cidx]     = s2;
            red_w[(r + 8) * 13 + cidx + 1] = s3;
            if (cidx < 4) {
                red_w[r * 13 + 8 + cidx]           = acc[17][0];
                red_w[r * 13 + 9 + cidx]           = acc[17][1];
                red_w[(r + 8) * 13 + 8 + cidx]     = acc[17][2];
                red_w[(r + 8) * 13 + 9 + cidx]     = acc[17][3];
            }
        }
        __syncwarp();

        // ---- softmax: lanes 0-15, node = lane
        if (lane < 16) {
            long ng = (long)g * 16 + lane;
            int cn = ng < N ? (int)ng : N - 1;
            float i0 = (float)g_ind0[cn];
            float i1 = (float)g_ind1[cn];
            const float* rw = &red_w[lane * 13];
            float sv[4], sf[4], al[4];
            #pragma unroll
            for (int h = 0; h < 4; h++) {
                sv[h] = rw[h]; sf[h] = rw[4 + h]; al[h] = rw[8 + h];
            }
            float bta[3][4];
            #pragma unroll
            for (int jr = 0; jr < 3; jr++) {
                float x[4];
                #pragma unroll
                for (int h = 0; h < 4; h++) {
                    float ar = (jr == 0) ? i0 * sv[h] : (jr == 1) ? i1 * sv[h] : sf[h];
                    float xx = al[h] + ar;
                    x[h] = (xx > 0.f) ? xx : 0.2f * xx;
                }
                float mx = fmaxf(fmaxf(x[0], x[1]), fmaxf(x[2], x[3]));
                float e0 = __expf(x[0] - mx), e1 = __expf(x[1] - mx);
                float e2 = __expf(x[2] - mx), e3 = __expf(x[3] - mx);
                float inv = 1.f / (e0 + e1 + e2 + e3);
                bta[jr][0] = e0 * inv; bta[jr][1] = e1 * inv;
                bta[jr][2] = e2 * inv; bta[jr][3] = e3 * inv;
            }
            #pragma unroll
            for (int h = 0; h < 4; h++) {
                gbuf_w[lane * 9 + h]     = bta[0][h] * i0 + bta[1][h] * i1;
                gbuf_w[lane * 9 + 4 + h] = bta[2][h];
            }
        }
        __syncwarp();

        // ---- epilogue: out = relu(g01*(v+br) + b2*feat), feat re-read (L1/L2 hot)
        #pragma unroll
        for (int hg = 0; hg < 4; hg++) {
            float g01a = gbuf_w[r * 9 + hg];
            float g01b = gbuf_w[(r + 8) * 9 + hg];
            float b2a  = gbuf_w[r * 9 + 4 + hg];
            float b2b  = gbuf_w[(r + 8) * 9 + 4 + hg];
            #pragma unroll
            for (int ii = 0; ii < 4; ii++) {
                int gnt = hg * 4 + ii;
                int tc2 = gnt * 4 + q;           // float2 index; col = 2*tc2
                float2 brv = *(const float2*)&br_s[tc2 * 2];
                float2 fa = __ldg((const float2*)(feat + c0n * 128) + tc2);
                float2 fb = __ldg((const float2*)(feat + c1n * 128) + tc2);
                float v0 = acc[gnt][0] + brv.x;
                float v1 = acc[gnt][1] + brv.y;
                float v2 = acc[gnt][2] + brv.x;
                float v3 = acc[gnt][3] + brv.y;
                if (n0 < N) {
                    float o0 = fmaxf(fmaf(g01a, v0, b2a * fa.x), 0.f);
                    float o1 = fmaxf(fmaf(g01a, v1, b2a * fa.y), 0.f);
                    *(float2*)&out[n0 * 128 + tc2 * 2] = make_float2(o0, o1);
                }
                if (n1 < N) {
                    float o2 = fmaxf(fmaf(g01b, v2, b2b * fb.x), 0.f);
                    float o3 = fmaxf(fmaf(g01b, v3, b2b * fb.y), 0.f);
                    *(float2*)&out[n1 * 128 + tc2 * 2] = make_float2(o2, o3);
                }
            }
        }
        __syncwarp();   // red_w/gbuf_w safe to overwrite next group
    }
}

extern "C" void kernel_launch(void* const* d_in, const int* in_sizes, int n_in,
                              void* d_out, int out_size) {
    // Inputs: feat, Wl, bl, Wr, br, attn_l, attn_r, rel_attn_l, rel_attn_r,
    //         alpha, src0, dst0, src1, dst1
    const float* feat = (const float*)d_in[0];
    const float* Wr   = (const float*)d_in[3];
    const float* br   = (const float*)d_in[4];
    const float* rl   = (const float*)d_in[7];
    const float* rr   = (const float*)d_in[8];
    const int* dst0   = (const int*)d_in[11];
    const int* dst1   = (const int*)d_in[13];
    float* out        = (float*)d_out;

    const int N  = in_sizes[0] / 128;
    const int E0 = in_sizes[11];
    const int E1 = in_sizes[13];

    const int SMEM_BYTES = SMEM_U32 * 4;
    cudaFuncSetAttribute(fused_kernel,
                         cudaFuncAttributeMaxDynamicSharedMemorySize, SMEM_BYTES);
    int nsm = 148;
    cudaDeviceGetAttribute(&nsm, cudaDevAttrMultiProcessorCount, 0);
    int T = (N + 127) >> 7;
    int grid = nsm < T ? nsm : T;
    fused_kernel<<<grid, 512, SMEM_BYTES>>>(feat, Wr, br, rl, rr,
                                            dst0, E0, dst1, E1, out, N);
}

// round 12
// speedup vs baseline: 1.2931x; 1.0168x over previous
#include <cuda_runtime.h>
#include <cuda_fp16.h>
#include <cstdint>

#define MAXN 100096

__device__ unsigned char g_ind0[MAXN];
__device__ unsigned char g_ind1[MAXN];
__device__ volatile unsigned int g_bar;
__device__ unsigned int g_tilectr;

// f16 x f16 -> f32 mma
__device__ __forceinline__ void mma_f16(float* c, const unsigned* a, const unsigned* b) {
    asm volatile(
        "mma.sync.aligned.m16n8k16.row.col.f32.f16.f16.f32 "
        "{%0,%1,%2,%3},{%4,%5,%6,%7},{%8,%9},{%0,%1,%2,%3};\n"
        : "+f"(c[0]), "+f"(c[1]), "+f"(c[2]), "+f"(c[3])
        : "r"(a[0]), "r"(a[1]), "r"(a[2]), "r"(a[3]), "r"(b[0]), "r"(b[1]));
}

// fp32 pair -> packed fp16x2 (RN)
__device__ __forceinline__ unsigned cvt2h(float2 f) {
    unsigned h;
    asm("cvt.rn.f16x2.f32 %0, %1, %2;" : "=r"(h) : "f"(f.y), "f"(f.x));
    return h;
}

// Software grid barrier: grid <= #SMs, 1 block/SM -> all co-resident.
__device__ __forceinline__ void grid_bar(unsigned nb) {
    __syncthreads();
    if (threadIdx.x == 0) {
        __threadfence();
        unsigned old = atomicAdd((unsigned*)&g_bar, 1u);
        unsigned target = (old / nb + 1u) * nb;
        while (g_bar < target) { }
        __threadfence();
    }
    __syncthreads();
}

// smem layout (u32 units)
#define BF_OFF    0        // 9216 : B-ext frags fp16 (18 n-tiles x 8 kc x 32 x uint2)
#define RED_OFF   9216     // 3328 : per-warp extras, 16 warps x 16 nodes x pitch 13
#define GBUF_OFF  12544    // 2304 : per-warp g01/b2, 16 warps x 16 nodes x pitch 9
#define BRS_OFF   14848    // 128
#define QS_OFF    14976    // 512
#define CHS_OFF   15488    // 8
#define SMEM_U32  15496    // 61984 bytes

// Persistent kernel. Flag phases use grid barriers; main loop is fully
// warp-autonomous: each warp steals a 16-node group (atomicAdd) and runs
// MMA -> softmax -> epilogue privately (only __syncwarp; NO __syncthreads).
// Single-term fp16 MMA (A and B both RN-rounded to fp16).
__global__ void __launch_bounds__(512, 1) fused_kernel(
    const float* __restrict__ feat, const float* __restrict__ Wr,
    const float* __restrict__ br, const float* __restrict__ rl,
    const float* __restrict__ rr,
    const int* __restrict__ d0, int E0, const int* __restrict__ d1, int E1,
    float* __restrict__ out, int N)
{
    extern __shared__ unsigned smem_u[];
    unsigned* BF = smem_u + BF_OFF;
    float* red  = (float*)(smem_u + RED_OFF);
    float* gbuf = (float*)(smem_u + GBUF_OFF);
    float* br_s = (float*)(smem_u + BRS_OFF);
    float* q_s  = (float*)(smem_u + QS_OFF);
    float* ch_s = (float*)(smem_u + CHS_OFF);

    const int tid  = threadIdx.x;
    const int lane = tid & 31;
    const int warp = tid >> 5;
    const unsigned nb = gridDim.x;

    // ---- phase 0: zero flags; reset tile counter
    for (int i = blockIdx.x * 512 + tid; i < MAXN / 4; i += nb * 512) {
        ((unsigned*)g_ind0)[i] = 0u;
        ((unsigned*)g_ind1)[i] = 0u;
    }
    if (blockIdx.x == 0 && tid == 0) g_tilectr = 0u;
    grid_bar(nb);

    // ---- phase 1: mark flags
    for (int i = blockIdx.x * 512 + tid; i < E0 + E1; i += nb * 512) {
        if (i < E0) g_ind0[d0[i]] = 1;
        else        g_ind1[d1[i - E0]] = 1;
    }

    // ---- prologue (overlaps other blocks' marking)
    if (tid < 128) br_s[tid] = br[tid];
    __syncthreads();
    if (tid < 512) {
        int h = tid >> 7, k = tid & 127;
        float s = 0.f;
        #pragma unroll 4
        for (int t = 0; t < 32; t++)
            s += __ldg(&Wr[(h * 32 + t) * 128 + k]) * __ldg(&rr[h * 32 + t]);
        q_s[tid] = s;
    }
    if (tid < 4) {
        float s = 0.f;
        for (int t = 0; t < 32; t++)
            s += __ldg(&br[tid * 32 + t]) * __ldg(&rr[tid * 32 + t]);
        ch_s[tid] = s;
    }
    __syncthreads();

    // B-ext fragments (single fp16): t'<128 Wr; 128-131 q_h; 132-135 rr
    // head-masked; 136-139 rl head-masked; 140-143 zero. mma fragment layout.
    for (int i = tid; i < 9216; i += 512) {
        int j  = i & 1;
        int ln = (i >> 1) & 31;
        int kc = (i >> 6) & 7;
        int nt = i >> 9;
        int tp = nt * 8 + (ln >> 2);
        int k0 = kc * 16 + (ln & 3) * 2 + j * 8;
        float v[2];
        #pragma unroll
        for (int e = 0; e < 2; e++) {
            int k = k0 + e;
            float x;
            if (tp < 128)      x = __ldg(&Wr[tp * 128 + k]);
            else if (tp < 132) x = q_s[(tp - 128) * 128 + k];
            else if (tp < 136) x = ((k >> 5) == (tp - 132)) ? __ldg(&rr[k]) : 0.f;
            else if (tp < 140) x = ((k >> 5) == (tp - 136)) ? __ldg(&rl[k]) : 0.f;
            else               x = 0.f;
            v[e] = x;
        }
        BF[i] = cvt2h(make_float2(v[0], v[1]));
    }

    grid_bar(nb);   // marking done everywhere; B frags visible

    // ---- main loop: warp-autonomous 16-node groups
    const int T16 = (N + 15) >> 4;
    const uint2* bp = ((const uint2*)BF) + lane;
    float* red_w  = red  + warp * 208;   // 16 nodes x pitch 13
    float* gbuf_w = gbuf + warp * 144;   // 16 nodes x pitch 9
    const int r = lane >> 2;
    const int q = lane & 3;

    for (;;) {
        unsigned g;
        if (lane == 0) g = atomicAdd(&g_tilectr, 1u);
        g = __shfl_sync(0xffffffffu, g, 0);
        if (g >= (unsigned)T16) break;

        long n0 = (long)g * 16 + r;
        long n1 = n0 + 8;
        long c0n = n0 > N - 1 ? N - 1 : n0;
        long c1n = n1 > N - 1 ? N - 1 : n1;
        const float2* f0p = (const float2*)(feat + c0n * 128) + q;
        const float2* f1p = (const float2*)(feat + c1n * 128) + q;

        float acc[18][4];
        #pragma unroll
        for (int i = 0; i < 18; i++)
            #pragma unroll
            for (int c = 0; c < 4; c++) acc[i][c] = 0.f;

        // A streamed per kc with 1-deep prefetch (rows r, r+8 of the group)
        float2 a = __ldg(f0p), b = __ldg(f1p);
        float2 c = __ldg(f0p + 4), d = __ldg(f1p + 4);
        #pragma unroll
        for (int kc = 0; kc < 8; kc++) {
            uint4 Ah;
            Ah.x = cvt2h(a);
            Ah.y = cvt2h(b);
            Ah.z = cvt2h(c);
            Ah.w = cvt2h(d);
            if (kc < 7) {
                a = __ldg(f0p + (kc + 1) * 8);
                b = __ldg(f1p + (kc + 1) * 8);
                c = __ldg(f0p + (kc + 1) * 8 + 4);
                d = __ldg(f1p + (kc + 1) * 8 + 4);
            }
            #pragma unroll
            for (int i = 0; i < 18; i++) {
                uint2 bb = bp[(i * 8 + kc) * 32];
                mma_f16(acc[i], (const unsigned*)&Ah, (const unsigned*)&bb);
            }
        }

        // ---- extras -> per-warp smem (acc16: sv cols0-3 (+ch), sf cols4-7;
        //      acc17: al cols0-3). Rows r (c0,c1) and r+8 (c2,c3).
        {
            int cidx = q * 2;
            float s0 = acc[16][0], s1 = acc[16][1];
            float s2 = acc[16][2], s3 = acc[16][3];
            if (cidx < 4) {
                float cA = ch_s[cidx], cB = ch_s[cidx + 1];
                s0 += cA; s1 += cB; s2 += cA; s3 += cB;
            }
            red_w[r * 13 + cidx]           = s0;
            red_w[r * 13 + cidx + 1]       = s1;
            red_w[(r + 8) * 13 + cidx]     = s2;
            red_w[(r + 8) * 13 + cidx + 1] = s3;
            if (cidx < 4) {
                red_w[r * 13 + 8 + cidx]           = acc[17][0];
                red_w[r * 13 + 9 + cidx]           = acc[17][1];
                red_w[(r + 8) * 13 + 8 + cidx]     = acc[17][2];
                red_w[(r + 8) * 13 + 9 + cidx]     = acc[17][3];
            }
        }
        __syncwarp();

        // ---- softmax: lanes 0-15, node = lane
        if (lane < 16) {
            long ng = (long)g * 16 + lane;
            int cn = ng < N ? (int)ng : N - 1;
            float i0 = (float)g_ind0[cn];
            float i1 = (float)g_ind1[cn];
            const float* rw = &red_w[lane * 13];
            float sv[4], sf[4], al[4];
            #pragma unroll
            for (int h = 0; h < 4; h++) {
                sv[h] = rw[h]; sf[h] = rw[4 + h]; al[h] = rw[8 + h];
            }
            float bta[3][4];
            #pragma unroll
            for (int jr = 0; jr < 3; jr++) {
                float x[4];
                #pragma unroll
                for (int h = 0; h < 4; h++) {
                    float ar = (jr == 0) ? i0 * sv[h] : (jr == 1) ? i1 * sv[h] : sf[h];
                    float xx = al[h] + ar;
                    x[h] = (xx > 0.f) ? xx : 0.2f * xx;
                }
                float mx = fmaxf(fmaxf(x[0], x[1]), fmaxf(x[2], x[3]));
                float e0 = __expf(x[0] - mx), e1 = __expf(x[1] - mx);
                float e2 = __expf(x[2] - mx), e3 = __expf(x[3] - mx);
                float inv = 1.f / (e0 + e1 + e2 + e3);
                bta[jr][0] = e0 * inv; bta[jr][1] = e1 * inv;
                bta[jr][2] = e2 * inv; bta[jr][3] = e3 * inv;
            }
            #pragma unroll
            for (int h = 0; h < 4; h++) {
                gbuf_w[lane * 9 + h]     = bta[0][h] * i0 + bta[1][h] * i1;
                gbuf_w[lane * 9 + 4 + h] = bta[2][h];
            }
        }
        __syncwarp();

        // ---- epilogue: out = relu(g01*(v+br) + b2*feat), feat re-read (L1 hot)
        #pragma unroll
        for (int hg = 0; hg < 4; hg++) {
            float g01a = gbuf_w[r * 9 + hg];
            float g01b = gbuf_w[(r + 8) * 9 + hg];
            float b2a  = gbuf_w[r * 9 + 4 + hg];
            float b2b  = gbuf_w[(r + 8) * 9 + 4 + hg];
            #pragma unroll
            for (int ii = 0; ii < 4; ii++) {
                int gnt = hg * 4 + ii;
                int tc2 = gnt * 4 + q;           // float2 index; col = 2*tc2
                float2 brv = *(const float2*)&br_s[tc2 * 2];
                float2 fa = __ldg((const float2*)(feat + c0n * 128) + tc2);
                float2 fb = __ldg((const float2*)(feat + c1n * 128) + tc2);
                float v0 = acc[gnt][0] + brv.x;
                float v1 = acc[gnt][1] + brv.y;
                float v2 = acc[gnt][2] + brv.x;
                float v3 = acc[gnt][3] + brv.y;
                if (n0 < N) {
                    float o0 = fmaxf(fmaf(g01a, v0, b2a * fa.x), 0.f);
                    float o1 = fmaxf(fmaf(g01a, v1, b2a * fa.y), 0.f);
                    *(float2*)&out[n0 * 128 + tc2 * 2] = make_float2(o0, o1);
                }
                if (n1 < N) {
                    float o2 = fmaxf(fmaf(g01b, v2, b2b * fb.x), 0.f);
                    float o3 = fmaxf(fmaf(g01b, v3, b2b * fb.y), 0.f);
                    *(float2*)&out[n1 * 128 + tc2 * 2] = make_float2(o2, o3);
                }
            }
        }
        __syncwarp();   // red_w/gbuf_w safe to overwrite next group
    }
}

extern "C" void kernel_launch(void* const* d_in, const int* in_sizes, int n_in,
                              void* d_out, int out_size) {
    // Inputs: feat, Wl, bl, Wr, br, attn_l, attn_r, rel_attn_l, rel_attn_r,
    //         alpha, src0, dst0, src1, dst1
    const float* feat = (const float*)d_in[0];
    const float* Wr   = (const float*)d_in[3];
    const float* br   = (const float*)d_in[4];
    const float* rl   = (const float*)d_in[7];
    const float* rr   = (const float*)d_in[8];
    const int* dst0   = (const int*)d_in[11];
    const int* dst1   = (const int*)d_in[13];
    float* out        = (float*)d_out;

    const int N  = in_sizes[0] / 128;
    const int E0 = in_sizes[11];
    const int E1 = in_sizes[13];

    const int SMEM_BYTES = SMEM_U32 * 4;
    cudaFuncSetAttribute(fused_kernel,
                         cudaFuncAttributeMaxDynamicSharedMemorySize, SMEM_BYTES);
    int nsm = 148;
    cudaDeviceGetAttribute(&nsm, cudaDevAttrMultiProcessorCount, 0);
    int T = (N + 127) >> 7;
    int grid = nsm < T ? nsm : T;
    fused_kernel<<<grid, 512, SMEM_BYTES>>>(feat, Wr, br, rl, rr,
                                            dst0, E0, dst1, E1, out, N);
}